// round 13
// baseline (speedup 1.0000x reference)
#include <cuda_runtime.h>

// SpatialGRU wavefront v10: 4-way batch split -> 256 CTAs x 224 threads,
// 2 CTAs/SM co-resident. v9's dependency-split cell (HT+HD before the wait,
// HL+GEMM2 after). Quarter q handles batch rows q*16..q*16+15.

namespace cfg {
constexpr int SM_HT = 0;        // 16x64
constexpr int SM_P0 = 1024;     // ping
constexpr int SM_P1 = 2048;     // pong
constexpr int SM_RR = 3072;     // 16x192
constexpr int SM_Z  = 6144;     // 16x256 -> ends 10240
constexpr int SM_W2 = 10240;    // 192x64 -> ends 22528
constexpr int SM_FLOATS = 22528;
constexpr int SM_BYTES = SM_FLOATS * 4;   // 90112
}

__device__ __align__(16) float g_s[(size_t)4096 * 64 * 512];   // [cell][b][512]
__device__ __align__(16) float g_h[(size_t)4096 * 64 * 64];    // [cell][b][u]
__device__ __align__(16) float g_wtrz[192 * 448];              // [k][n]
__device__ __align__(16) float g_wt2[192 * 64];                // [k][n] (U_w^T)
__device__ __align__(16) float g_wx[16 * 512];                 // [c][n]
__device__ __align__(16) float g_bias[512];
__device__ int g_flag[256];                                    // [q*64 + r]

// ---------------- helpers ----------------------------------------------------
__device__ __forceinline__ unsigned long long f2_pack(float lo, float hi) {
    unsigned long long d;
    asm("mov.b64 %0, {%1, %2};" : "=l"(d) : "f"(lo), "f"(hi));
    return d;
}
__device__ __forceinline__ unsigned long long f2_dup(float a) {
    unsigned long long d;
    asm("mov.b64 %0, {%1, %1};" : "=l"(d) : "f"(a));
    return d;
}
__device__ __forceinline__ float2 f2_unpack(unsigned long long v) {
    float2 r;
    asm("mov.b64 {%0, %1}, %2;" : "=f"(r.x), "=f"(r.y) : "l"(v));
    return r;
}
__device__ __forceinline__ unsigned long long f2_fma(unsigned long long a,
                                                     unsigned long long b,
                                                     unsigned long long c) {
    unsigned long long d;
    asm("fma.rn.f32x2 %0, %1, %2, %3;" : "=l"(d) : "l"(a), "l"(b), "l"(c));
    return d;
}
__device__ __forceinline__ unsigned long long f2_add(unsigned long long a,
                                                     unsigned long long b) {
    unsigned long long d;
    asm("add.rn.f32x2 %0, %1, %2;" : "=l"(d) : "l"(a), "l"(b));
    return d;
}
__device__ __forceinline__ int ld_acq(const int* p) {
    int v;
    asm volatile("ld.global.acquire.gpu.b32 %0, [%1];" : "=r"(v) : "l"(p) : "memory");
    return v;
}
__device__ __forceinline__ void st_rel(int* p, int v) {
    asm volatile("st.global.release.gpu.b32 [%0], %1;" :: "l"(p), "r"(v) : "memory");
}
__device__ __forceinline__ float fsigmoid(float x) { return 1.f / (1.f + __expf(-x)); }

// ---------------- setup ------------------------------------------------------
__global__ void k_nop() {}

__global__ void k_prep(const float* __restrict__ wr_w, const float* __restrict__ wz_w,
                       const float* __restrict__ wij_w, const float* __restrict__ U_w,
                       const float* __restrict__ wr_b, const float* __restrict__ wz_b,
                       const float* __restrict__ wij_b) {
    int idx = blockIdx.x * 256 + threadIdx.x;   // 418*256 = 107008 exact
    const int T1 = 192 * 448, T2 = T1 + 192 * 64, T3 = T2 + 16 * 512;
    if (idx < T1) {
        int k = idx / 448, n = idx % 448;
        g_wtrz[idx] = (n < 192) ? wr_w[n * 208 + k] : wz_w[(n - 192) * 208 + k];
    } else if (idx < T2) {
        int i2 = idx - T1;
        int k = i2 / 64, n = i2 % 64;
        g_wt2[i2] = U_w[n * 192 + k];
    } else if (idx < T3) {
        int i2 = idx - T2;
        int c = i2 / 512, n = i2 % 512;
        g_wx[i2] = (n < 192)   ? wr_w[n * 208 + 192 + c]
                 : (n < 448) ? wz_w[(n - 192) * 208 + 192 + c]
                             : wij_w[(n - 448) * 16 + c];
    } else {
        int n = idx - T3;
        g_bias[n] = (n < 192) ? wr_b[n] : (n < 448) ? wz_b[n - 192] : wij_b[n - 448];
    }
    if (idx < 256) g_flag[idx] = 0;
}

// g_s[cell][row][col] = sum_c x[row][c] * Wx[c][col] + bias[col]
__global__ __launch_bounds__(256) void k_sxz(const float* __restrict__ inputs) {
    __shared__ float sW[16 * 512];
    __shared__ float sb[512];
    __shared__ float sx[64 * 16];
    const int cell = blockIdx.x;
    const int tid = threadIdx.x;
    for (int i = tid; i < 8192; i += 256) sW[i] = g_wx[i];
    for (int i = tid; i < 512; i += 256) sb[i] = g_bias[i];
    for (int i = tid; i < 1024; i += 256) sx[i] = inputs[(size_t)i * 4096 + cell];
    __syncthreads();
    const int ryq = tid >> 4, cx = tid & 15;
    const int row0 = ryq * 4;
    float* outp = g_s + (size_t)cell * 64 * 512;
#pragma unroll 1
    for (int p = 0; p < 4; ++p) {
        const int col0 = p * 128 + cx * 8;
        unsigned long long acc[4][4];
        {
            float4 b0 = *reinterpret_cast<const float4*>(&sb[col0]);
            float4 b1 = *reinterpret_cast<const float4*>(&sb[col0 + 4]);
            unsigned long long p0 = f2_pack(b0.x, b0.y), p1 = f2_pack(b0.z, b0.w);
            unsigned long long p2 = f2_pack(b1.x, b1.y), p3 = f2_pack(b1.z, b1.w);
#pragma unroll
            for (int i = 0; i < 4; ++i) {
                acc[i][0] = p0; acc[i][1] = p1; acc[i][2] = p2; acc[i][3] = p3;
            }
        }
#pragma unroll
        for (int k = 0; k < 16; k += 4) {
            float4 a[4];
#pragma unroll
            for (int i = 0; i < 4; ++i)
                a[i] = *reinterpret_cast<const float4*>(&sx[(row0 + i) * 16 + k]);
#pragma unroll
            for (int kk = 0; kk < 4; ++kk) {
                ulonglong2 w0 = *reinterpret_cast<const ulonglong2*>(sW + (k + kk) * 512 + col0);
                ulonglong2 w1 = *reinterpret_cast<const ulonglong2*>(sW + (k + kk) * 512 + col0 + 4);
#pragma unroll
                for (int i = 0; i < 4; ++i) {
                    unsigned long long d = f2_dup(reinterpret_cast<const float*>(&a[i])[kk]);
                    acc[i][0] = f2_fma(d, w0.x, acc[i][0]);
                    acc[i][1] = f2_fma(d, w0.y, acc[i][1]);
                    acc[i][2] = f2_fma(d, w1.x, acc[i][2]);
                    acc[i][3] = f2_fma(d, w1.y, acc[i][3]);
                }
            }
        }
#pragma unroll
        for (int i = 0; i < 4; ++i) {
            float2 u0 = f2_unpack(acc[i][0]), u1 = f2_unpack(acc[i][1]);
            float2 u2 = f2_unpack(acc[i][2]), u3 = f2_unpack(acc[i][3]);
            float4 o0 = {u0.x, u0.y, u1.x, u1.y};
            float4 o1 = {u2.x, u2.y, u3.x, u3.y};
            *reinterpret_cast<float4*>(&outp[(row0 + i) * 512 + col0]) = o0;
            *reinterpret_cast<float4*>(&outp[(row0 + i) * 512 + col0 + 4]) = o1;
        }
    }
}

// ---- GEMM1 K=64 segment: 8 rows x 4 cols, W lanes line-contiguous ----------
__device__ __forceinline__ void gemm1_seg(const float* __restrict__ A, int row0,
                                          const float* __restrict__ Wc,
                                          unsigned long long acc[8][2]) {
#pragma unroll 4
    for (int k = 0; k < 64; k += 4) {
        ulonglong2 w[4];
#pragma unroll
        for (int kk = 0; kk < 4; ++kk)
            w[kk] = *reinterpret_cast<const ulonglong2*>(Wc + (k + kk) * 448);
#pragma unroll
        for (int half = 0; half < 2; ++half) {
            float4 a[4];
#pragma unroll
            for (int i = 0; i < 4; ++i)
                a[i] = *reinterpret_cast<const float4*>(
                    &A[(row0 + half * 4 + i) * 64 + k]);
#pragma unroll
            for (int kk = 0; kk < 4; ++kk) {
#pragma unroll
                for (int i = 0; i < 4; ++i) {
                    unsigned long long d =
                        f2_dup(reinterpret_cast<const float*>(&a[i])[kk]);
                    acc[half * 4 + i][0] = f2_fma(d, w[kk].x, acc[half * 4 + i][0]);
                    acc[half * 4 + i][1] = f2_fma(d, w[kk].y, acc[half * 4 + i][1]);
                }
            }
        }
    }
}

// ---------------- wavefront kernel -------------------------------------------
__global__ __launch_bounds__(224, 2) void k_wave(float* __restrict__ out) {
    extern __shared__ float sm[];
    float* sHT = sm + cfg::SM_HT;
    float* sRR = sm + cfg::SM_RR;
    float* sZ  = sm + cfg::SM_Z;
    float* sW2 = sm + cfg::SM_W2;

    const int tid = threadIdx.x;
    const int bid = blockIdx.x;
    const int r = bid & 63, q = bid >> 6;       // quarter 0..3
    const int rb0 = q * 16;                     // batch-row base
    const int cg = tid % 112, rg = tid / 112;   // GEMM1: col-fast mapping
    const int col0 = cg * 4;                    // 4 cols/thread
    const int row0 = rg * 8;                    // 8 rows/thread (of 16)
    const int blk = col0 >> 6, off = col0 & 63;
    const int tx2 = tid & 7, ty2 = tid >> 3;    // GEMM2 (tid < 128): 1r x 8c
    const int lc0 = 8 * tx2;

    for (int i = tid; i < 3 * 1024; i += 224) sm[i] = 0.f;   // HT, P0, P1 = 0
    for (int i = tid; i < 3072; i += 224)                    // stage U_w^T once
        reinterpret_cast<float4*>(sW2)[i] =
            reinterpret_cast<const float4*>(g_wt2)[i];
    __syncthreads();

#pragma unroll 1
    for (int l = 0; l < 64; ++l) {
        float* sHL = sm + ((l & 1) ? cfg::SM_P1 : cfg::SM_P0);
        float* sHD = sm + ((l & 1) ? cfg::SM_P0 : cfg::SM_P1);

        const size_t cellbase = (size_t)(l * 64 + r) * 64 * 512;

        // issue g_s loads first; consumed only after the pre-segments
        float4 sv[8];
        {
            const float* sp = g_s + cellbase + (size_t)(rb0 + row0) * 512 + col0;
#pragma unroll
            for (int i = 0; i < 8; ++i)
                sv[i] = *reinterpret_cast<const float4*>(sp + i * 512);
        }
        float4 sv2a, sv2b;
        if (tid < 128) {
            const float* sp2 = g_s + cellbase + (size_t)(rb0 + ty2) * 512 + 448 + lc0;
            sv2a = *reinterpret_cast<const float4*>(sp2);
            sv2b = *reinterpret_cast<const float4*>(sp2 + 4);
        }

        // ---- PRE (independent of h_left): HT + HD segments of GEMM1 ----
        unsigned long long acc[8][2];
#pragma unroll
        for (int i = 0; i < 8; ++i) { acc[i][0] = 0ull; acc[i][1] = 0ull; }
        gemm1_seg(sHT, row0, g_wtrz + col0, acc);                // h_top
        gemm1_seg(sHD, row0, g_wtrz + 128 * 448 + col0, acc);    // h_diag
#pragma unroll
        for (int i = 0; i < 8; ++i) {                            // += s (x-proj)
            acc[i][0] = f2_add(acc[i][0], f2_pack(sv[i].x, sv[i].y));
            acc[i][1] = f2_add(acc[i][1], f2_pack(sv[i].z, sv[i].w));
        }

        // ---- wait for left neighbor, then load h_left ----
        if (r > 0) {
            if (tid == 0) {
                while (ld_acq(&g_flag[q * 64 + r - 1]) < l + 1) __nanosleep(32);
            }
            __syncthreads();
            const float4* src = reinterpret_cast<const float4*>(
                g_h + ((size_t)(l * 64 + (r - 1)) * 64 + rb0) * 64);
            float4* dst = reinterpret_cast<float4*>(sHL);
            for (int i = tid; i < 256; i += 224) dst[i] = src[i];
            __syncthreads();
        }

        // ---- POST: h_left segment of GEMM1 + epilogue ----
        gemm1_seg(sHL, row0, g_wtrz + 64 * 448 + col0, acc);     // h_left

        if (blk < 3) {
            const float* HU = (blk == 0) ? sHL : (blk == 1) ? sHT : sHD;
#pragma unroll
            for (int i = 0; i < 8; ++i) {
                int row = row0 + i;
                float2 u0 = f2_unpack(acc[i][0]), u1 = f2_unpack(acc[i][1]);
                float4 hu = *reinterpret_cast<const float4*>(&HU[row * 64 + off]);
                float4 o = {hu.x * fsigmoid(u0.x), hu.y * fsigmoid(u0.y),
                            hu.z * fsigmoid(u1.x), hu.w * fsigmoid(u1.y)};
                *reinterpret_cast<float4*>(&sRR[row * 192 + blk * 64 + off]) = o;
            }
        } else {
#pragma unroll
            for (int i = 0; i < 8; ++i) {
                int row = row0 + i;
                float2 u0 = f2_unpack(acc[i][0]), u1 = f2_unpack(acc[i][1]);
                float4 o = {u0.x, u0.y, u1.x, u1.y};
                *reinterpret_cast<float4*>(&sZ[row * 256 + (blk - 3) * 64 + off]) = o;
            }
        }
        __syncthreads();

        // ---- GEMM2 (tid < 128): rr*hu @ U_w^T + s[:,448:], gates, h ----
        if (tid < 128) {
            unsigned long long a0 = f2_pack(sv2a.x, sv2a.y);
            unsigned long long a1 = f2_pack(sv2a.z, sv2a.w);
            unsigned long long a2 = f2_pack(sv2b.x, sv2b.y);
            unsigned long long a3 = f2_pack(sv2b.z, sv2b.w);
            const float* A0 = sRR + ty2 * 192;
            const float* Wc = sW2 + lc0;
#pragma unroll 4
            for (int k = 0; k < 192; k += 4) {
                float4 a = *reinterpret_cast<const float4*>(&A0[k]);
#pragma unroll
                for (int kk = 0; kk < 4; ++kk) {
                    ulonglong2 w0 = *reinterpret_cast<const ulonglong2*>(Wc + (k + kk) * 64);
                    ulonglong2 w1 = *reinterpret_cast<const ulonglong2*>(Wc + (k + kk) * 64 + 4);
                    unsigned long long d = f2_dup(reinterpret_cast<const float*>(&a)[kk]);
                    a0 = f2_fma(d, w0.x, a0);
                    a1 = f2_fma(d, w0.y, a1);
                    a2 = f2_fma(d, w1.x, a2);
                    a3 = f2_fma(d, w1.y, a3);
                }
            }

            const int row = ty2;
            unsigned long long accp[4] = {a0, a1, a2, a3};
#pragma unroll
            for (int c = 0; c < 2; ++c) {
                const int cc = lc0 + c * 4;
                float2 v01 = f2_unpack(accp[2 * c]), v23 = f2_unpack(accp[2 * c + 1]);
                float hn[4] = {tanhf(v01.x), tanhf(v01.y), tanhf(v23.x), tanhf(v23.y)};
                const float* zr = sZ + row * 256 + cc;
                float4 zi4 = *reinterpret_cast<const float4*>(zr);
                float4 zl4 = *reinterpret_cast<const float4*>(zr + 64);
                float4 zt4 = *reinterpret_cast<const float4*>(zr + 128);
                float4 zd4 = *reinterpret_cast<const float4*>(zr + 192);
                float4 hl4 = *reinterpret_cast<const float4*>(&sHL[row * 64 + cc]);
                float4 ht4 = *reinterpret_cast<const float4*>(&sHT[row * 64 + cc]);
                float4 hd4 = *reinterpret_cast<const float4*>(&sHD[row * 64 + cc]);
                float zi[4] = {zi4.x, zi4.y, zi4.z, zi4.w};
                float zl[4] = {zl4.x, zl4.y, zl4.z, zl4.w};
                float zt[4] = {zt4.x, zt4.y, zt4.z, zt4.w};
                float zd[4] = {zd4.x, zd4.y, zd4.z, zd4.w};
                float hl[4] = {hl4.x, hl4.y, hl4.z, hl4.w};
                float ht[4] = {ht4.x, ht4.y, ht4.z, ht4.w};
                float hd[4] = {hd4.x, hd4.y, hd4.z, hd4.w};
                float h[4];
#pragma unroll
                for (int j = 0; j < 4; ++j) {
                    float m = fmaxf(fmaxf(zi[j], zl[j]), fmaxf(zt[j], zd[j]));
                    float ei = __expf(zi[j] - m), el = __expf(zl[j] - m);
                    float et = __expf(zt[j] - m), ed = __expf(zd[j] - m);
                    float inv = 1.f / (ei + el + et + ed);
                    h[j] = (el * hl[j] + et * ht[j] + ed * hd[j] + ei * hn[j]) * inv;
                }
                float4 h4 = {h[0], h[1], h[2], h[3]};
                *reinterpret_cast<float4*>(&sHT[row * 64 + cc]) = h4;
                if (r < 63)
                    *reinterpret_cast<float4*>(
                        g_h + ((size_t)(l * 64 + r) * 64 + rb0 + row) * 64 + cc) = h4;
                if (l == 63 && r == 63)
                    *reinterpret_cast<float4*>(out + (rb0 + row) * 64 + cc) = h4;
            }
        }
        __syncthreads();   // orders all stores before the release below
        if (tid == 0) st_rel(&g_flag[q * 64 + r], l + 1);
    }
}

// ---------------- launch ------------------------------------------------------
extern "C" void kernel_launch(void* const* d_in, const int* in_sizes, int n_in,
                              void* d_out, int out_size) {
    const float* inputs = (const float*)d_in[0];
    const float* wr_w = (const float*)d_in[1];
    const float* wr_b = (const float*)d_in[2];
    const float* wz_w = (const float*)d_in[3];
    const float* wz_b = (const float*)d_in[4];
    const float* wij_w = (const float*)d_in[5];
    const float* wij_b = (const float*)d_in[6];
    const float* U_w = (const float*)d_in[7];
    float* out = (float*)d_out;

    cudaFuncSetAttribute(k_wave, cudaFuncAttributeMaxDynamicSharedMemorySize,
                         cfg::SM_BYTES);

    k_nop<<<1, 1>>>();
    k_prep<<<418, 256>>>(wr_w, wz_w, wij_w, U_w, wr_b, wz_b, wij_b);
    k_sxz<<<4096, 256>>>(inputs);
    k_wave<<<256, 224, cfg::SM_BYTES>>>(out);
}

// round 14
// speedup vs baseline: 1.3854x; 1.3854x over previous
#include <cuda_runtime.h>

// SpatialGRU wavefront v11: v9 dependency-split core, 896 threads with an
// in-CTA COLUMN split (224 col-threads x 4 rowgroups, 8 rows x 2 cols each).
// W bytes per CTA identical to v9; warps/SMSP doubled to 7.

namespace cfg {
constexpr int SM_HT = 0;        // 32x64
constexpr int SM_P0 = 2048;     // ping
constexpr int SM_P1 = 4096;     // pong
constexpr int SM_RR = 6144;     // 32x192
constexpr int SM_Z  = 12288;    // 32x256 -> ends 20480
constexpr int SM_W2 = 20480;    // 192x64 -> ends 32768
constexpr int SM_FLOATS = 32768;
constexpr int SM_BYTES = SM_FLOATS * 4;   // 131072
}

__device__ __align__(16) float g_s[(size_t)4096 * 64 * 512];   // [cell][b][512]
__device__ __align__(16) float g_h[(size_t)4096 * 64 * 64];    // [cell][b][u]
__device__ __align__(16) float g_wtrz[192 * 448];              // [k][n]
__device__ __align__(16) float g_wt2[192 * 64];                // [k][n] (U_w^T)
__device__ __align__(16) float g_wx[16 * 512];                 // [c][n]
__device__ __align__(16) float g_bias[512];
__device__ int g_flag[128];                                    // [half*64 + r]

// ---------------- helpers ----------------------------------------------------
__device__ __forceinline__ unsigned long long f2_pack(float lo, float hi) {
    unsigned long long d;
    asm("mov.b64 %0, {%1, %2};" : "=l"(d) : "f"(lo), "f"(hi));
    return d;
}
__device__ __forceinline__ unsigned long long f2_dup(float a) {
    unsigned long long d;
    asm("mov.b64 %0, {%1, %1};" : "=l"(d) : "f"(a));
    return d;
}
__device__ __forceinline__ float2 f2_unpack(unsigned long long v) {
    float2 r;
    asm("mov.b64 {%0, %1}, %2;" : "=f"(r.x), "=f"(r.y) : "l"(v));
    return r;
}
__device__ __forceinline__ unsigned long long f2_fma(unsigned long long a,
                                                     unsigned long long b,
                                                     unsigned long long c) {
    unsigned long long d;
    asm("fma.rn.f32x2 %0, %1, %2, %3;" : "=l"(d) : "l"(a), "l"(b), "l"(c));
    return d;
}
__device__ __forceinline__ unsigned long long f2_add(unsigned long long a,
                                                     unsigned long long b) {
    unsigned long long d;
    asm("add.rn.f32x2 %0, %1, %2;" : "=l"(d) : "l"(a), "l"(b));
    return d;
}
__device__ __forceinline__ int ld_acq(const int* p) {
    int v;
    asm volatile("ld.global.acquire.gpu.b32 %0, [%1];" : "=r"(v) : "l"(p) : "memory");
    return v;
}
__device__ __forceinline__ void st_rel(int* p, int v) {
    asm volatile("st.global.release.gpu.b32 [%0], %1;" :: "l"(p), "r"(v) : "memory");
}
__device__ __forceinline__ float fsigmoid(float x) { return 1.f / (1.f + __expf(-x)); }

// ---------------- setup ------------------------------------------------------
__global__ void k_nop() {}

__global__ void k_prep(const float* __restrict__ wr_w, const float* __restrict__ wz_w,
                       const float* __restrict__ wij_w, const float* __restrict__ U_w,
                       const float* __restrict__ wr_b, const float* __restrict__ wz_b,
                       const float* __restrict__ wij_b) {
    int idx = blockIdx.x * 256 + threadIdx.x;   // 418*256 = 107008 exact
    const int T1 = 192 * 448, T2 = T1 + 192 * 64, T3 = T2 + 16 * 512;
    if (idx < T1) {
        int k = idx / 448, n = idx % 448;
        g_wtrz[idx] = (n < 192) ? wr_w[n * 208 + k] : wz_w[(n - 192) * 208 + k];
    } else if (idx < T2) {
        int i2 = idx - T1;
        int k = i2 / 64, n = i2 % 64;
        g_wt2[i2] = U_w[n * 192 + k];
    } else if (idx < T3) {
        int i2 = idx - T2;
        int c = i2 / 512, n = i2 % 512;
        g_wx[i2] = (n < 192)   ? wr_w[n * 208 + 192 + c]
                 : (n < 448) ? wz_w[(n - 192) * 208 + 192 + c]
                             : wij_w[(n - 448) * 16 + c];
    } else {
        int n = idx - T3;
        g_bias[n] = (n < 192) ? wr_b[n] : (n < 448) ? wz_b[n - 192] : wij_b[n - 448];
    }
    if (idx < 128) g_flag[idx] = 0;
}

// g_s[cell][row][col] = sum_c x[row][c] * Wx[c][col] + bias[col]
__global__ __launch_bounds__(256) void k_sxz(const float* __restrict__ inputs) {
    __shared__ float sW[16 * 512];
    __shared__ float sb[512];
    __shared__ float sx[64 * 16];
    const int cell = blockIdx.x;
    const int tid = threadIdx.x;
    for (int i = tid; i < 8192; i += 256) sW[i] = g_wx[i];
    for (int i = tid; i < 512; i += 256) sb[i] = g_bias[i];
    for (int i = tid; i < 1024; i += 256) sx[i] = inputs[(size_t)i * 4096 + cell];
    __syncthreads();
    const int ryq = tid >> 4, cx = tid & 15;
    const int row0 = ryq * 4;
    float* outp = g_s + (size_t)cell * 64 * 512;
#pragma unroll 1
    for (int p = 0; p < 4; ++p) {
        const int col0 = p * 128 + cx * 8;
        unsigned long long acc[4][4];
        {
            float4 b0 = *reinterpret_cast<const float4*>(&sb[col0]);
            float4 b1 = *reinterpret_cast<const float4*>(&sb[col0 + 4]);
            unsigned long long p0 = f2_pack(b0.x, b0.y), p1 = f2_pack(b0.z, b0.w);
            unsigned long long p2 = f2_pack(b1.x, b1.y), p3 = f2_pack(b1.z, b1.w);
#pragma unroll
            for (int i = 0; i < 4; ++i) {
                acc[i][0] = p0; acc[i][1] = p1; acc[i][2] = p2; acc[i][3] = p3;
            }
        }
#pragma unroll
        for (int k = 0; k < 16; k += 4) {
            float4 a[4];
#pragma unroll
            for (int i = 0; i < 4; ++i)
                a[i] = *reinterpret_cast<const float4*>(&sx[(row0 + i) * 16 + k]);
#pragma unroll
            for (int kk = 0; kk < 4; ++kk) {
                ulonglong2 w0 = *reinterpret_cast<const ulonglong2*>(sW + (k + kk) * 512 + col0);
                ulonglong2 w1 = *reinterpret_cast<const ulonglong2*>(sW + (k + kk) * 512 + col0 + 4);
#pragma unroll
                for (int i = 0; i < 4; ++i) {
                    unsigned long long d = f2_dup(reinterpret_cast<const float*>(&a[i])[kk]);
                    acc[i][0] = f2_fma(d, w0.x, acc[i][0]);
                    acc[i][1] = f2_fma(d, w0.y, acc[i][1]);
                    acc[i][2] = f2_fma(d, w1.x, acc[i][2]);
                    acc[i][3] = f2_fma(d, w1.y, acc[i][3]);
                }
            }
        }
#pragma unroll
        for (int i = 0; i < 4; ++i) {
            float2 u0 = f2_unpack(acc[i][0]), u1 = f2_unpack(acc[i][1]);
            float2 u2 = f2_unpack(acc[i][2]), u3 = f2_unpack(acc[i][3]);
            float4 o0 = {u0.x, u0.y, u1.x, u1.y};
            float4 o1 = {u2.x, u2.y, u3.x, u3.y};
            *reinterpret_cast<float4*>(&outp[(row0 + i) * 512 + col0]) = o0;
            *reinterpret_cast<float4*>(&outp[(row0 + i) * 512 + col0 + 4]) = o1;
        }
    }
}

// ---- GEMM1 K=64 segment: 8 rows x 2 cols per thread ------------------------
__device__ __forceinline__ void gemm1_seg(const float* __restrict__ A, int row0,
                                          const float* __restrict__ Wc,
                                          unsigned long long acc[8]) {
#pragma unroll 4
    for (int k = 0; k < 64; k += 4) {
        unsigned long long w[4];
#pragma unroll
        for (int kk = 0; kk < 4; ++kk)
            w[kk] = *reinterpret_cast<const unsigned long long*>(Wc + (k + kk) * 448);
#pragma unroll
        for (int half = 0; half < 2; ++half) {
            float4 a[4];
#pragma unroll
            for (int i = 0; i < 4; ++i)
                a[i] = *reinterpret_cast<const float4*>(
                    &A[(row0 + half * 4 + i) * 64 + k]);
#pragma unroll
            for (int kk = 0; kk < 4; ++kk) {
#pragma unroll
                for (int i = 0; i < 4; ++i) {
                    unsigned long long d =
                        f2_dup(reinterpret_cast<const float*>(&a[i])[kk]);
                    acc[half * 4 + i] = f2_fma(d, w[kk], acc[half * 4 + i]);
                }
            }
        }
    }
}

// ---------------- wavefront kernel -------------------------------------------
__global__ __launch_bounds__(896, 1) void k_wave(float* __restrict__ out) {
    extern __shared__ float sm[];
    float* sHT = sm + cfg::SM_HT;
    float* sRR = sm + cfg::SM_RR;
    float* sZ  = sm + cfg::SM_Z;
    float* sW2 = sm + cfg::SM_W2;

    const int tid = threadIdx.x;
    const int bid = blockIdx.x;
    const int r = bid & 63, half = bid >> 6;
    const int rb0 = half * 32;                  // batch-row base
    const int cg = tid % 224, rg = tid / 224;   // col-fast mapping
    const int col0 = cg * 2;                    // 2 cols/thread
    const int row0 = rg * 8;                    // 8 rows/thread (of 32)
    const int blk = col0 >> 6, off = col0 & 63;
    const int tx2 = tid & 15, ty2 = tid >> 4;   // GEMM2 (tid < 256)
    const int lc0 = 4 * tx2;

    for (int i = tid; i < 3 * 2048; i += 896) sm[i] = 0.f;   // HT, P0, P1 = 0
    for (int i = tid; i < 3072; i += 896)                    // stage U_w^T once
        reinterpret_cast<float4*>(sW2)[i] =
            reinterpret_cast<const float4*>(g_wt2)[i];
    __syncthreads();

#pragma unroll 1
    for (int l = 0; l < 64; ++l) {
        float* sHL = sm + ((l & 1) ? cfg::SM_P1 : cfg::SM_P0);
        float* sHD = sm + ((l & 1) ? cfg::SM_P0 : cfg::SM_P1);

        const size_t cellbase = (size_t)(l * 64 + r) * 64 * 512;

        // issue g_s loads first; consumed only after the pre-segments
        float2 sv[8];
        {
            const float* sp = g_s + cellbase + (size_t)(rb0 + row0) * 512 + col0;
#pragma unroll
            for (int i = 0; i < 8; ++i)
                sv[i] = *reinterpret_cast<const float2*>(sp + i * 512);
        }
        float4 sv2a, sv2b;
        if (tid < 256) {
            sv2a = *reinterpret_cast<const float4*>(
                g_s + cellbase + (size_t)(rb0 + ty2) * 512 + 448 + lc0);
            sv2b = *reinterpret_cast<const float4*>(
                g_s + cellbase + (size_t)(rb0 + ty2 + 16) * 512 + 448 + lc0);
        }

        // ---- PRE (independent of h_left): HT + HD segments of GEMM1 ----
        unsigned long long acc[8];
#pragma unroll
        for (int i = 0; i < 8; ++i) acc[i] = 0ull;
        gemm1_seg(sHT, row0, g_wtrz + col0, acc);                // h_top
        gemm1_seg(sHD, row0, g_wtrz + 128 * 448 + col0, acc);    // h_diag
#pragma unroll
        for (int i = 0; i < 8; ++i)                              // += s (x-proj)
            acc[i] = f2_add(acc[i], f2_pack(sv[i].x, sv[i].y));

        // ---- wait for left neighbor, then load h_left ----
        if (r > 0) {
            if (tid == 0) {
                while (ld_acq(&g_flag[half * 64 + r - 1]) < l + 1) __nanosleep(32);
            }
            __syncthreads();
            const float4* src = reinterpret_cast<const float4*>(
                g_h + ((size_t)(l * 64 + (r - 1)) * 64 + rb0) * 64);
            float4* dst = reinterpret_cast<float4*>(sHL);
            for (int i = tid; i < 512; i += 896) dst[i] = src[i];
            __syncthreads();
        }

        // ---- POST: h_left segment of GEMM1 + epilogue ----
        gemm1_seg(sHL, row0, g_wtrz + 64 * 448 + col0, acc);     // h_left

        if (blk < 3) {
            const float* HU = (blk == 0) ? sHL : (blk == 1) ? sHT : sHD;
#pragma unroll
            for (int i = 0; i < 8; ++i) {
                int row = row0 + i;
                float2 u = f2_unpack(acc[i]);
                float2 hu = *reinterpret_cast<const float2*>(&HU[row * 64 + off]);
                float2 o = {hu.x * fsigmoid(u.x), hu.y * fsigmoid(u.y)};
                *reinterpret_cast<float2*>(&sRR[row * 192 + blk * 64 + off]) = o;
            }
        } else {
#pragma unroll
            for (int i = 0; i < 8; ++i) {
                int row = row0 + i;
                float2 u = f2_unpack(acc[i]);
                *reinterpret_cast<float2*>(&sZ[row * 256 + (blk - 3) * 64 + off]) = u;
            }
        }
        __syncthreads();

        // ---- GEMM2 (tid < 256): rr*hu @ U_w^T + s[:,448:], gates, h ----
        if (tid < 256) {
            unsigned long long acc0[2], acc1[2];
            acc0[0] = f2_pack(sv2a.x, sv2a.y);
            acc1[0] = f2_pack(sv2a.z, sv2a.w);
            acc0[1] = f2_pack(sv2b.x, sv2b.y);
            acc1[1] = f2_pack(sv2b.z, sv2b.w);
            const float* A0 = sRR + ty2 * 192;
            const float* A1 = sRR + (ty2 + 16) * 192;
            const float* Wc = sW2 + lc0;
#pragma unroll 4
            for (int k = 0; k < 192; k += 4) {
                float4 a0 = *reinterpret_cast<const float4*>(&A0[k]);
                float4 a1 = *reinterpret_cast<const float4*>(&A1[k]);
#pragma unroll
                for (int kk = 0; kk < 4; ++kk) {
                    ulonglong2 w = *reinterpret_cast<const ulonglong2*>(
                        Wc + (k + kk) * 64);
                    unsigned long long d0 =
                        f2_dup(reinterpret_cast<const float*>(&a0)[kk]);
                    unsigned long long d1 =
                        f2_dup(reinterpret_cast<const float*>(&a1)[kk]);
                    acc0[0] = f2_fma(d0, w.x, acc0[0]);
                    acc1[0] = f2_fma(d0, w.y, acc1[0]);
                    acc0[1] = f2_fma(d1, w.x, acc0[1]);
                    acc1[1] = f2_fma(d1, w.y, acc1[1]);
                }
            }

#pragma unroll
            for (int i = 0; i < 2; ++i) {
                int row = ty2 + 16 * i;
                float2 v01 = f2_unpack(acc0[i]), v23 = f2_unpack(acc1[i]);
                float hn[4] = {tanhf(v01.x), tanhf(v01.y), tanhf(v23.x), tanhf(v23.y)};
                const float* zr = sZ + row * 256 + lc0;
                float4 zi4 = *reinterpret_cast<const float4*>(zr);
                float4 zl4 = *reinterpret_cast<const float4*>(zr + 64);
                float4 zt4 = *reinterpret_cast<const float4*>(zr + 128);
                float4 zd4 = *reinterpret_cast<const float4*>(zr + 192);
                float4 hl4 = *reinterpret_cast<const float4*>(&sHL[row * 64 + lc0]);
                float4 ht4 = *reinterpret_cast<const float4*>(&sHT[row * 64 + lc0]);
                float4 hd4 = *reinterpret_cast<const float4*>(&sHD[row * 64 + lc0]);
                float zi[4] = {zi4.x, zi4.y, zi4.z, zi4.w};
                float zl[4] = {zl4.x, zl4.y, zl4.z, zl4.w};
                float zt[4] = {zt4.x, zt4.y, zt4.z, zt4.w};
                float zd[4] = {zd4.x, zd4.y, zd4.z, zd4.w};
                float hl[4] = {hl4.x, hl4.y, hl4.z, hl4.w};
                float ht[4] = {ht4.x, ht4.y, ht4.z, ht4.w};
                float hd[4] = {hd4.x, hd4.y, hd4.z, hd4.w};
                float h[4];
#pragma unroll
                for (int j = 0; j < 4; ++j) {
                    float m = fmaxf(fmaxf(zi[j], zl[j]), fmaxf(zt[j], zd[j]));
                    float ei = __expf(zi[j] - m), el = __expf(zl[j] - m);
                    float et = __expf(zt[j] - m), ed = __expf(zd[j] - m);
                    float inv = 1.f / (ei + el + et + ed);
                    h[j] = (el * hl[j] + et * ht[j] + ed * hd[j] + ei * hn[j]) * inv;
                }
                float4 h4 = {h[0], h[1], h[2], h[3]};
                *reinterpret_cast<float4*>(&sHT[row * 64 + lc0]) = h4;
                if (r < 63)
                    *reinterpret_cast<float4*>(
                        g_h + ((size_t)(l * 64 + r) * 64 + rb0 + row) * 64 + lc0) = h4;
                if (l == 63 && r == 63)
                    *reinterpret_cast<float4*>(out + (rb0 + row) * 64 + lc0) = h4;
            }
        }
        __syncthreads();   // orders all stores before the release below
        if (tid == 0) st_rel(&g_flag[half * 64 + r], l + 1);
    }
}

// ---------------- launch ------------------------------------------------------
extern "C" void kernel_launch(void* const* d_in, const int* in_sizes, int n_in,
                              void* d_out, int out_size) {
    const float* inputs = (const float*)d_in[0];
    const float* wr_w = (const float*)d_in[1];
    const float* wr_b = (const float*)d_in[2];
    const float* wz_w = (const float*)d_in[3];
    const float* wz_b = (const float*)d_in[4];
    const float* wij_w = (const float*)d_in[5];
    const float* wij_b = (const float*)d_in[6];
    const float* U_w = (const float*)d_in[7];
    float* out = (float*)d_out;

    cudaFuncSetAttribute(k_wave, cudaFuncAttributeMaxDynamicSharedMemorySize,
                         cfg::SM_BYTES);

    k_nop<<<1, 1>>>();
    k_prep<<<418, 256>>>(wr_w, wz_w, wij_w, U_w, wr_b, wz_b, wij_b);
    k_sxz<<<4096, 256>>>(inputs);
    k_wave<<<128, 896, cfg::SM_BYTES>>>(out);
}